// round 4
// baseline (speedup 1.0000x reference)
#include <cuda_runtime.h>

// LIF forward scan:
//   v_t = BETA * v_{t-1} * (1 - s_{t-1}) + i_t   (hard reset)
//   s_t = (v_t >= 1.0)
// Outputs: spikes (B,T,H), membrane (B,T,H), v_final (B,H) — concatenated in d_out.
//
// Latency-bound: 32768 independent chains. Rolling register prefetch keeps a
// CONSTANT U loads in flight per warp (vs block prefetch whose in-flight count
// decays to zero during each compute block — the R3 duty-cycle loss).

#define LIF_BETA 0.904837f

static constexpr int Bc = 16;
static constexpr int Tc = 1024;
static constexpr int Hc = 2048;
static constexpr int U  = 64;     // rolling prefetch distance

__global__ __launch_bounds__(32)
void lif_kernel(const float* __restrict__ in,   // (B, T, H)
                const float* __restrict__ v0,   // (B, H)
                float* __restrict__ out)        // [spikes | membrane | v_final]
{
    const int idx = blockIdx.x * 32 + threadIdx.x;   // idx = b*H + h
    if (idx >= Bc * Hc) return;

    const int b = idx >> 11;        // / 2048
    const int h = idx & (Hc - 1);   // % 2048

    const size_t plane = (size_t)Bc * Tc * Hc;
    float* __restrict__ spikes = out;
    float* __restrict__ mem    = out + plane;
    float* __restrict__ vfin   = out + 2 * plane;

    const size_t base = (size_t)b * Tc * Hc + h;

    float v = v0[idx];
    float s = 0.0f;

    float cur[U];

    // Warm: first U inputs in flight before any compute.
#pragma unroll
    for (int u = 0; u < U; ++u)
        cur[u] = __ldcs(in + base + (size_t)u * Hc);

    // Main loop: consume cur[u] for step tb+u, immediately reload the slot
    // with step tb+U+u. One LDG issued per step -> constant U in flight.
    for (int tb = 0; tb < Tc - U; tb += U) {
#pragma unroll
        for (int u = 0; u < U; ++u) {
            const float x = cur[u];
            cur[u] = __ldcs(in + base + (size_t)(tb + U + u) * Hc);

            const float vr = (s != 0.0f) ? 0.0f : v;   // hard reset, s in {0,1}
            v = fmaf(LIF_BETA, vr, x);
            s = (v >= 1.0f) ? 1.0f : 0.0f;
            const size_t o = base + (size_t)(tb + u) * Hc;
            __stcs(spikes + o, s);
            __stcs(mem + o, v);
        }
    }

    // Peeled final block: no further loads.
    {
        const int tb = Tc - U;
#pragma unroll
        for (int u = 0; u < U; ++u) {
            const float vr = (s != 0.0f) ? 0.0f : v;
            v = fmaf(LIF_BETA, vr, cur[u]);
            s = (v >= 1.0f) ? 1.0f : 0.0f;
            const size_t o = base + (size_t)(tb + u) * Hc;
            __stcs(spikes + o, s);
            __stcs(mem + o, v);
        }
    }

    vfin[idx] = v;
}

extern "C" void kernel_launch(void* const* d_in, const int* in_sizes, int n_in,
                              void* d_out, int out_size)
{
    const float* input = (const float*)d_in[0];   // (16, 1024, 2048) float32
    const float* v0    = (const float*)d_in[1];   // (16, 2048) float32
    float* out         = (float*)d_out;

    const int nthreads = Bc * Hc;                 // 32768 chains
    const int block = 32;
    const int grid  = (nthreads + block - 1) / block;  // 1024 blocks, ~7/SM
    lif_kernel<<<grid, block>>>(input, v0, out);
}